// round 8
// baseline (speedup 1.0000x reference)
#include <cuda_runtime.h>

// Problem constants (fixed by setup_inputs)
#define BB   2
#define NN   16384
#define CC   64
#define SS   4096
#define KK   32
#define R2   0.16f
#define CIN  67
#define H3   128

#define OUT_F (BB*SS*3)              /* 24576  : new_xyz region     */
#define OUT_I (OUT_F + BB*H3*SS)     /* 1073152: samp_idx region    */

#define CPG   4                      /* centroids per block group        */
#define ROWS  (CPG*KK)               /* 128 rows per group               */
#define GRPS  (BB*SS/CPG)            /* 2048 groups                      */
#define ASTR  130                    /* act row stride (floats), even    */
#define ASTU  65                     /* act row stride (ull)             */

// Scratch (device globals — no allocation allowed)
__device__ float4 g_pts[BB*NN];          // x,y,z,|p|^2
__device__ float  g_featT[BB*NN*CC];     // [B][N][C]
__device__ int    g_idx[BB*SS*KK];       // ball query result

// ---- packed f32x2 helpers (FFMA2 via PTX) ---------------------------------
typedef unsigned long long ull;
__device__ __forceinline__ void upk2(ull v, float& lo, float& hi) {
    asm("mov.b64 {%0,%1},%2;" : "=f"(lo), "=f"(hi) : "l"(v));
}
__device__ __forceinline__ ull pk2(float lo, float hi) {
    ull r; asm("mov.b64 %0,{%1,%2};" : "=l"(r) : "f"(lo), "f"(hi)); return r;
}
__device__ __forceinline__ ull ffma2(ull a, ull b, ull c) {
    ull d; asm("fma.rn.f32x2 %0,%1,%2,%3;" : "=l"(d) : "l"(a), "l"(b), "l"(c));
    return d;
}
__device__ __forceinline__ ull ldp(const float* p) {   // aligned smem pair
    return *reinterpret_cast<const ull*>(p);
}

// ---------------------------------------------------------------------------
__global__ void k_prep(const float* __restrict__ xyz) {
    int i = blockIdx.x * blockDim.x + threadIdx.x;
    if (i < BB*NN) {
        float x = xyz[3*i+0], y = xyz[3*i+1], z = xyz[3*i+2];
        g_pts[i] = make_float4(x, y, z, fmaf(z, z, fmaf(y, y, x*x)));
    }
}

// Transpose features [B,C,N] -> [B,N,C]
__global__ void k_trans(const float* __restrict__ feat) {
    __shared__ float tile[32][33];
    int b  = blockIdx.z;
    int n0 = blockIdx.x * 32, c0 = blockIdx.y * 32;
    int tx = threadIdx.x, ty = threadIdx.y;
    #pragma unroll
    for (int i = ty; i < 32; i += 8)
        tile[i][tx] = feat[(size_t)b*CC*NN + (size_t)(c0+i)*NN + (n0+tx)];
    __syncthreads();
    #pragma unroll
    for (int i = ty; i < 32; i += 8)
        g_featT[(size_t)b*NN*CC + (size_t)(n0+i)*CC + (c0+tx)] = tile[tx][i];
}

// new_xyz copy + samp_idx
__global__ void k_outs(const float* __restrict__ xyz, float* __restrict__ out) {
    int i = blockIdx.x * blockDim.x + threadIdx.x;
    if (i < BB*SS) {
        int b = i / SS, s = i % SS;
        out[3*i+0] = xyz[(size_t)(b*NN+s)*3 + 0];
        out[3*i+1] = xyz[(size_t)(b*NN+s)*3 + 1];
        out[3*i+2] = xyz[(size_t)(b*NN+s)*3 + 2];
        out[OUT_I + i] = (float)s;
    }
}

// ---------------------------------------------------------------------------
// Ball query: TWO warps per centroid, each scans one half of N with the
// proven x4-unrolled ordered ballot scan; then an ordered merge (half A's
// indices all precede half B's) reproduces first-KK-in-index-order exactly.
// Empty slots fill with the overall first hit (0 if none).
__global__ void k_ball() {
    __shared__ int sbuf[8][KK];
    __shared__ int scnt[8];
    int w    = threadIdx.x >> 5;        // warp 0..7
    int lane = threadIdx.x & 31;
    int cw   = w >> 1;                  // centroid within block 0..3
    int half = w & 1;
    int gw   = blockIdx.x * 4 + cw;
    int b    = gw / SS, s = gw % SS;
    int base0 = b * NN;
    float4 c4 = g_pts[base0 + s];
    unsigned lmask = (1u << lane) - 1u;
    unsigned lbit  = 1u << lane;
    int cnt = 0;
    const int start = half * (NN/2), end = start + NN/2;
    for (int base = start; base < end; base += 128) {
        float4 p0 = g_pts[base0 + base + lane];
        float4 p1 = g_pts[base0 + base + 32  + lane];
        float4 p2 = g_pts[base0 + base + 64  + lane];
        float4 p3 = g_pts[base0 + base + 96  + lane];
        float d0 = c4.w + p0.w - 2.0f*(c4.x*p0.x + c4.y*p0.y + c4.z*p0.z);
        float d1 = c4.w + p1.w - 2.0f*(c4.x*p1.x + c4.y*p1.y + c4.z*p1.z);
        float d2 = c4.w + p2.w - 2.0f*(c4.x*p2.x + c4.y*p2.y + c4.z*p2.z);
        float d3 = c4.w + p3.w - 2.0f*(c4.x*p3.x + c4.y*p3.y + c4.z*p3.z);
        unsigned m0 = __ballot_sync(0xffffffffu, d0 < R2);
        unsigned m1 = __ballot_sync(0xffffffffu, d1 < R2);
        unsigned m2 = __ballot_sync(0xffffffffu, d2 < R2);
        unsigned m3 = __ballot_sync(0xffffffffu, d3 < R2);
        if (m0 & lbit) {
            int pos = cnt + __popc(m0 & lmask);
            if (pos < KK) sbuf[w][pos] = base + lane;
        }
        cnt += __popc(m0);
        if (m1 & lbit) {
            int pos = cnt + __popc(m1 & lmask);
            if (pos < KK) sbuf[w][pos] = base + 32 + lane;
        }
        cnt += __popc(m1);
        if (m2 & lbit) {
            int pos = cnt + __popc(m2 & lmask);
            if (pos < KK) sbuf[w][pos] = base + 64 + lane;
        }
        cnt += __popc(m2);
        if (m3 & lbit) {
            int pos = cnt + __popc(m3 & lmask);
            if (pos < KK) sbuf[w][pos] = base + 96 + lane;
        }
        cnt += __popc(m3);
        if (cnt >= KK) break;
    }
    if (lane == 0) scnt[w] = cnt;
    __syncthreads();
    if (half == 0) {
        int cA = min(scnt[w],     KK);
        int cB = min(scnt[w + 1], KK);
        int first;
        if      (cA > 0) first = sbuf[w][0];
        else if (cB > 0) first = sbuf[w + 1][0];
        else             first = 0;
        int v = first;
        if      (lane < cA)      v = sbuf[w][lane];
        else if (lane - cA < cB) v = sbuf[w + 1][lane - cA];
        g_idx[gw*KK + lane] = v;
    }
}

// ---------------------------------------------------------------------------
// Fused gather + 3-layer MLP + max-pool. 4 centroids (128 rows) per group.
// Weights stored DUPLICATED as (w,w) pairs in smem: LDS.64 of a dup pair is a
// warp-broadcast (one crossbar access), so the hot loop is pure
// LDS.64 + FFMA2 with ZERO register packs and no duplicated traffic.
// acts [c][row] (stride 130), FFMA2 lanes = adjacent rows.
// tid = dgp*32 + rpg: warp dgp owns d = dgp+8j; lane rpg owns row-pairs
// rpg, rpg+32 (i.e. rows 2rpg..2rpg+1, 2rpg+64..2rpg+65).
__global__ void __launch_bounds__(256, 1) k_mlp(
    const float* __restrict__ W1, const float* __restrict__ b1,
    const float* __restrict__ W2, const float* __restrict__ b2,
    const float* __restrict__ W3, const float* __restrict__ b3,
    float* __restrict__ out)
{
    extern __shared__ float sm[];
    float2* sW1d = (float2*)sm;                 // 67*64 pairs  = 8576 floats
    float2* sW2d = sW1d + 67*64;                // 64*64 pairs  = 8192
    float2* sW3d = sW2d + 64*64;                // 64*128 pairs = 16384
    float2* sb1d = sW3d + 64*128;               // 64 pairs
    float2* sb2d = sb1d + 64;                   // 64 pairs
    float2* sb3d = sb2d + 64;                   // 128 pairs
    float*  actA = (float*)(sb3d + 128);        // 67 x 130 = 8710
    float*  actB = actA + 67*ASTR;              // 64 x 130 = 8320
    const int tid = threadIdx.x;
    const int dgp = tid >> 5;         // warp id = d group (0..7)
    const int rpg = tid & 31;         // lane   = row-pair (0..31)

    for (int i = tid; i < 67*64; i += 256) { float w = W1[i]; sW1d[i] = make_float2(w, w); }
    for (int i = tid; i < 64*64; i += 256) { float w = W2[i]; sW2d[i] = make_float2(w, w); }
    for (int i = tid; i < 64*128; i += 256){ float w = W3[i]; sW3d[i] = make_float2(w, w); }
    if (tid < 64)  { float v = b1[tid]; sb1d[tid] = make_float2(v, v);
                     v = b2[tid];       sb2d[tid] = make_float2(v, v); }
    if (tid < 128) { float v = b3[tid]; sb3d[tid] = make_float2(v, v); }
    __syncthreads();

    for (int grp = blockIdx.x; grp < GRPS; grp += gridDim.x) {
        // ---- gather: 2 threads per row (128 rows) ----
        {
            const int row = tid >> 1;            // 0..127
            const int sub = tid & 1;
            const int cent = grp*CPG + (row >> 5);
            const int b  = cent >> 12;
            const int s  = cent & (SS-1);
            const int bN = b * NN;
            const int k  = row & 31;
            int n = g_idx[cent*KK + k];
            if (sub == 0) {
                float4 p   = g_pts[bN + n];
                float4 ctr = g_pts[bN + s];
                actA[0*ASTR + row] = p.x - ctr.x;
                actA[1*ASTR + row] = p.y - ctr.y;
                actA[2*ASTR + row] = p.z - ctr.z;
            }
            const float4* fq = (const float4*)(g_featT + (size_t)(bN + n) * CC);
            #pragma unroll
            for (int q = 0; q < 8; q++) {
                float4 f4 = fq[sub*8 + q];
                int c = 3 + 4*(sub*8 + q);
                actA[(c    )*ASTR + row] = f4.x;
                actA[(c + 1)*ASTR + row] = f4.y;
                actA[(c + 2)*ASTR + row] = f4.z;
                actA[(c + 3)*ASTR + row] = f4.w;
            }
        }
        __syncthreads();

        // ---- layer 1: actA(67 x 128) -> actB(64 x 128), relu ----
        {
            ull acc[2][8];
            #pragma unroll
            for (int j = 0; j < 8; j++) {
                ull bb = ldp((const float*)(sb1d + dgp + 8*j));
                acc[0][j] = bb; acc[1][j] = bb;
            }
            #pragma unroll 2
            for (int c = 0; c < CIN; c++) {
                ull a0 = ldp(actA + c*ASTR + 2*rpg);
                ull a1 = ldp(actA + c*ASTR + 2*rpg + 64);
                #pragma unroll
                for (int j = 0; j < 8; j++) {
                    ull wv = ldp((const float*)(sW1d + c*64 + dgp + 8*j));
                    acc[0][j] = ffma2(a0, wv, acc[0][j]);
                    acc[1][j] = ffma2(a1, wv, acc[1][j]);
                }
            }
            ull* oB = (ull*)actB;
            #pragma unroll
            for (int j = 0; j < 8; j++) {
                float lo, hi;
                upk2(acc[0][j], lo, hi);
                oB[(size_t)(dgp + 8*j)*ASTU + rpg]      = pk2(fmaxf(lo,0.f), fmaxf(hi,0.f));
                upk2(acc[1][j], lo, hi);
                oB[(size_t)(dgp + 8*j)*ASTU + rpg + 32] = pk2(fmaxf(lo,0.f), fmaxf(hi,0.f));
            }
        }
        __syncthreads();

        // ---- layer 2: actB(64 x 128) -> actA(64 x 128), relu ----
        {
            ull acc[2][8];
            #pragma unroll
            for (int j = 0; j < 8; j++) {
                ull bb = ldp((const float*)(sb2d + dgp + 8*j));
                acc[0][j] = bb; acc[1][j] = bb;
            }
            #pragma unroll 2
            for (int c = 0; c < 64; c++) {
                ull a0 = ldp(actB + c*ASTR + 2*rpg);
                ull a1 = ldp(actB + c*ASTR + 2*rpg + 64);
                #pragma unroll
                for (int j = 0; j < 8; j++) {
                    ull wv = ldp((const float*)(sW2d + c*64 + dgp + 8*j));
                    acc[0][j] = ffma2(a0, wv, acc[0][j]);
                    acc[1][j] = ffma2(a1, wv, acc[1][j]);
                }
            }
            ull* oA = (ull*)actA;
            #pragma unroll
            for (int j = 0; j < 8; j++) {
                float lo, hi;
                upk2(acc[0][j], lo, hi);
                oA[(size_t)(dgp + 8*j)*ASTU + rpg]      = pk2(fmaxf(lo,0.f), fmaxf(hi,0.f));
                upk2(acc[1][j], lo, hi);
                oA[(size_t)(dgp + 8*j)*ASTU + rpg + 32] = pk2(fmaxf(lo,0.f), fmaxf(hi,0.f));
            }
        }
        __syncthreads();

        // ---- layer 3: actA(64 x 128) -> 128 d, relu + max over k ----
        #pragma unroll 1
        for (int h = 0; h < 2; h++) {
            ull acc[2][8];
            #pragma unroll
            for (int j = 0; j < 8; j++) {
                ull bb = ldp((const float*)(sb3d + dgp + 8*j + 64*h));
                acc[0][j] = bb; acc[1][j] = bb;
            }
            #pragma unroll 2
            for (int c = 0; c < 64; c++) {
                ull a0 = ldp(actA + c*ASTR + 2*rpg);
                ull a1 = ldp(actA + c*ASTR + 2*rpg + 64);
                #pragma unroll
                for (int j = 0; j < 8; j++) {
                    ull wv = ldp((const float*)(sW3d + c*128 + dgp + 8*j + 64*h));
                    acc[0][j] = ffma2(a0, wv, acc[0][j]);
                    acc[1][j] = ffma2(a1, wv, acc[1][j]);
                }
            }
            // relu + in-pair max + butterfly over k; rows 2p,2p+1 share a cent
            #pragma unroll
            for (int i = 0; i < 2; i++) {
                #pragma unroll
                for (int j = 0; j < 8; j++) {
                    float lo, hi; upk2(acc[i][j], lo, hi);
                    float m = fmaxf(fmaxf(lo, 0.f), fmaxf(hi, 0.f));
                    m = fmaxf(m, __shfl_xor_sync(0xffffffffu, m, 1));
                    m = fmaxf(m, __shfl_xor_sync(0xffffffffu, m, 2));
                    m = fmaxf(m, __shfl_xor_sync(0xffffffffu, m, 4));
                    m = fmaxf(m, __shfl_xor_sync(0xffffffffu, m, 8));
                    if ((rpg & 15) == 0) {
                        // pair index p = rpg + 32*i -> cent_local = p >> 4
                        int cent_local = (rpg >> 4) + 2*i;
                        int cent = grp*CPG + cent_local;
                        int b = cent >> 12, s = cent & (SS-1);
                        int d = dgp + 8*j + 64*h;
                        out[OUT_F + (size_t)b*H3*SS + (size_t)d*SS + s] = m;
                    }
                }
            }
        }
        __syncthreads();   // actA reused by next gather
    }
}

// ---------------------------------------------------------------------------
extern "C" void kernel_launch(void* const* d_in, const int* in_sizes, int n_in,
                              void* d_out, int out_size) {
    (void)in_sizes; (void)n_in; (void)out_size;
    const float* xyz  = (const float*)d_in[0];
    const float* feat = (const float*)d_in[1];
    const float* W1   = (const float*)d_in[2];
    const float* b1   = (const float*)d_in[3];
    const float* W2   = (const float*)d_in[4];
    const float* b2   = (const float*)d_in[5];
    const float* W3   = (const float*)d_in[6];
    const float* b3   = (const float*)d_in[7];
    float* out = (float*)d_out;

    // smem floats: dup weights 8576+8192+16384 + biases 128+128+256
    //            + actA 8710 + actB 8320 = 50694 -> 202776 B
    const int smem_mlp = 50694 * 4;
    cudaFuncSetAttribute(k_mlp, cudaFuncAttributeMaxDynamicSharedMemorySize, smem_mlp);

    k_prep<<<(BB*NN + 255)/256, 256>>>(xyz);
    k_trans<<<dim3(NN/32, CC/32, BB), dim3(32, 8)>>>(feat);
    k_outs<<<(BB*SS + 255)/256, 256>>>(xyz, out);
    k_ball<<<(BB*SS)/4, 256>>>();
    k_mlp<<<148, 256, smem_mlp>>>(W1, b1, W2, b2, W3, b3, out);
}